// round 8
// baseline (speedup 1.0000x reference)
#include <cuda_runtime.h>
#include <cstdint>
#include <cstddef>

#define B_ 32
#define S_ 4096
#define E_ 1024
#define H_ 16
#define D_ 64
#define NC 16            // chunks over s (256 rows each)
#define RPB 4            // rows per batch
#define NBAT 64          // 256 / RPB
#define NST 4            // cp.async ring stages
#define L2E 1.4426950408889634f

// ---------------- static scratch ----------------
__device__ float g_q[B_ * E_];
__device__ float g_qk[B_ * H_ * E_];
__device__ float g_ctxp[(size_t)NC * B_ * H_ * E_];   // unnormalized ctx per chunk
__device__ float g_m[NC * B_ * H_];
__device__ float g_d[NC * B_ * H_];

typedef unsigned long long u64;

__device__ __forceinline__ u64 pack2(float x, float y) {
    u64 p;
    asm("mov.b64 %0, {%1, %2};" : "=l"(p) : "f"(x), "f"(y));
    return p;
}
__device__ __forceinline__ void unpack2(u64 p, float& x, float& y) {
    asm("mov.b64 {%0, %1}, %2;" : "=f"(x), "=f"(y) : "l"(p));
}
__device__ __forceinline__ u64 ffma2(u64 a, u64 b, u64 c) {
    u64 d;
    asm("fma.rn.f32x2 %0, %1, %2, %3;" : "=l"(d) : "l"(a), "l"(b), "l"(c));
    return d;
}
__device__ __forceinline__ u64 fmul2(u64 a, u64 b) {
    u64 d;
    asm("mul.rn.f32x2 %0, %1, %2;" : "=l"(d) : "l"(a), "l"(b));
    return d;
}
__device__ __forceinline__ void cp16(uint32_t dst_smem, const void* src) {
    asm volatile("cp.async.cg.shared.global [%0], [%1], 16;" :: "r"(dst_smem), "l"(src));
}
__device__ __forceinline__ void cp_commit() { asm volatile("cp.async.commit_group;"); }
template <int N>
__device__ __forceinline__ void cp_wait() { asm volatile("cp.async.wait_group %0;" :: "n"(N)); }

// ---------------- K1: q = seq1@Wq + bq  (4 b per block) ----------------
// grid (4 jt, 8 bg) block 256
__global__ void k_qproj(const float* __restrict__ seq1, const float* __restrict__ Wq,
                        const float* __restrict__ bq) {
    int b0 = blockIdx.y * 4;
    int j = blockIdx.x * 256 + threadIdx.x;
    __shared__ __align__(16) float s1[4][E_];
#pragma unroll
    for (int bb = 0; bb < 4; bb++)
        ((float4*)s1[bb])[threadIdx.x] = ((const float4*)(seq1 + (size_t)(b0 + bb) * E_))[threadIdx.x];
    __syncthreads();
    float acc[4] = {0.f, 0.f, 0.f, 0.f};
#pragma unroll 4
    for (int e = 0; e < E_; e++) {
        float w = Wq[(size_t)e * E_ + j];
#pragma unroll
        for (int bb = 0; bb < 4; bb++) acc[bb] = fmaf(s1[bb][e], w, acc[bb]);
    }
    float bias = bq[j];
#pragma unroll
    for (int bb = 0; bb < 4; bb++) g_q[(b0 + bb) * E_ + j] = acc[bb] + bias;
}

// ---------------- K2: qk[b][h][e] = (Σ_d q[b][h*64+d]·Wk[e][h*64+d]) * 0.125 ----------------
__global__ void k_qk(const float* __restrict__ Wk) {
    int h = blockIdx.x;
    int e = blockIdx.y * 256 + threadIdx.x;
    __shared__ __align__(16) float2 sq[B_][D_ / 2];
    for (int i = threadIdx.x; i < B_ * (D_ / 2); i += 256) {
        int b = i >> 5, dp = i & 31;
        sq[b][dp] = ((const float2*)(g_q + b * E_ + h * D_))[dp];
    }
    __syncthreads();
    float2 wk[D_ / 2];
    const float2* wrow = (const float2*)(Wk + (size_t)e * E_ + h * D_);
#pragma unroll
    for (int i = 0; i < D_ / 2; i++) wk[i] = wrow[i];
#pragma unroll 4
    for (int b = 0; b < B_; b++) {
        float ax = 0.f, ay = 0.f;
#pragma unroll
        for (int i = 0; i < D_ / 2; i++) {
            float2 qv = sq[b][i];
            ax = fmaf(wk[i].x, qv.x, ax);
            ay = fmaf(wk[i].y, qv.y, ay);
        }
        g_qk[(b * H_ + h) * E_ + e] = (ax + ay) * 0.125f;
    }
}

// ---------------- pad kernel (keeps ncu sample index on k_fused) ----------------
__global__ void k_pad() {}

// ---------------- K3: fused scores + online softmax + ctx ----------------
// grid (NC, B_) block 512
// thread: hg = tid>>7 (heads hg*4+j), eidx = tid&127
//   e-slices: eL = eidx*4, eH = 512 + eidx*4  (conflict-free 16B lane stride)
// dyn smem: sx[NST][RPB][1024] (64KB) + spA[16][128][4] (32KB) + sp2[16][32][4] (8KB)
__global__ void __launch_bounds__(512, 1) k_fused(const float* __restrict__ seq2,
                                                  const int* __restrict__ mask) {
    extern __shared__ __align__(16) char dyn[];
    float* sx  = (float*)dyn;                      // [NST][RPB][1024]
    float* spA = (float*)(dyn + 65536);            // [(r*4+hg)][eidx][4]
    float* sp2 = (float*)(dyn + 65536 + 32768);    // [pair][lane][4]
    __shared__ float sw_[RPB][H_];
    __shared__ float sfac[H_];
    __shared__ float sm_m[H_], sm_d[H_];
    __shared__ uint32_t sball[8];

    int b = blockIdx.y;
    int chunk = blockIdx.x;
    int s0 = chunk * 256;
    int tid = threadIdx.x;
    int hg = tid >> 7;              // 0..3
    int eidx = tid & 127;           // 0..127

    if (tid < 256) {
        int mm = mask[b * S_ + s0 + tid];
        uint32_t bal = __ballot_sync(0xffffffffu, mm != 0);
        if ((tid & 31) == 0) sball[tid >> 5] = bal;
    }
    if (tid < H_) { sm_m[tid] = -1e30f; sm_d[tid] = 0.f; }

    // qk registers: 4 heads x (4 floats @ eL, 4 floats @ eH)
    u64 qk2[4][4];
#pragma unroll
    for (int j = 0; j < 4; j++) {
        const float* qb = g_qk + ((size_t)b * H_ + hg * 4 + j) * E_;
        float4 vL = *(const float4*)(qb + eidx * 4);
        float4 vH = *(const float4*)(qb + 512 + eidx * 4);
        qk2[j][0] = pack2(vL.x, vL.y);
        qk2[j][1] = pack2(vL.z, vL.w);
        qk2[j][2] = pack2(vH.x, vH.y);
        qk2[j][3] = pack2(vH.z, vH.w);
    }

    u64 ctx[4][4];
#pragma unroll
    for (int j = 0; j < 4; j++)
#pragma unroll
        for (int i = 0; i < 4; i++) ctx[j][i] = pack2(0.f, 0.f);

    uint32_t sx_addr = (uint32_t)__cvta_generic_to_shared(sx);
    const float* base = seq2 + ((size_t)b * S_ + s0) * E_;
    int prow = hg;                  // prefetch row 0..3
    int pcol = eidx;                // 128 threads x 8 floats per row

    __syncthreads();                // sball/sm_* visible

    // prologue: prefetch batches 0,1,2
#pragma unroll
    for (int nb = 0; nb < 3; nb++) {
        uint32_t flN = (sball[0] >> (nb * 4)) & 0xF;
        if ((flN >> prow) & 1) {
            const float* src = base + ((size_t)nb * RPB + prow) * E_ + pcol * 4;
            uint32_t dst = sx_addr + (uint32_t)(nb * RPB + prow) * 4096 + pcol * 16;
            cp16(dst, src);
            cp16(dst + 2048, src + 512);
        }
        cp_commit();
    }

    for (int bat = 0; bat < NBAT; bat++) {
        int stage = bat & 3;
        {   // prefetch bat+3 (one commit per iter keeps group accounting uniform)
            int nb = bat + 3;
            if (nb < NBAT) {
                uint32_t flN = (sball[nb >> 3] >> ((nb & 7) * 4)) & 0xF;
                if ((flN >> prow) & 1) {
                    const float* src = base + ((size_t)nb * RPB + prow) * E_ + pcol * 4;
                    uint32_t dst = sx_addr + (uint32_t)((nb & 3) * RPB + prow) * 4096 + pcol * 16;
                    cp16(dst, src);
                    cp16(dst + 2048, src + 512);
                }
            }
            cp_commit();
        }
        cp_wait<2>();
        __syncthreads();            // sync1: batch ready

        uint32_t fl = (sball[bat >> 3] >> ((bat & 7) * 4)) & 0xF;
        if (fl == 0) continue;      // block-uniform

        const float* xs = sx + stage * (RPB * 1024);
        u64 xr[RPB][4];

        // ---- Phase A: load rows once, per-head partial dots, STS float4 ----
#pragma unroll
        for (int r = 0; r < RPB; r++) {
            if ((fl >> r) & 1) {
                float4 vL = *(const float4*)(xs + r * 1024 + eidx * 4);
                float4 vH = *(const float4*)(xs + r * 1024 + 512 + eidx * 4);
                xr[r][0] = pack2(vL.x, vL.y);
                xr[r][1] = pack2(vL.z, vL.w);
                xr[r][2] = pack2(vH.x, vH.y);
                xr[r][3] = pack2(vH.z, vH.w);
                float pj[4];
#pragma unroll
                for (int j = 0; j < 4; j++) {
                    u64 a = fmul2(qk2[j][0], xr[r][0]);
                    a = ffma2(qk2[j][1], xr[r][1], a);
                    a = ffma2(qk2[j][2], xr[r][2], a);
                    a = ffma2(qk2[j][3], xr[r][3], a);
                    float ax, ay;
                    unpack2(a, ax, ay);
                    pj[j] = ax + ay;
                }
                *(float4*)(spA + ((r * 4 + hg) * 128 + eidx) * 4) =
                    make_float4(pj[0], pj[1], pj[2], pj[3]);
            }
        }
        __syncthreads();            // sync2: spA complete

        // ---- stage1: 128 -> 32 per (r,hg), float4-wide ----
        {
            int pair = tid >> 5, lane = tid & 31;
            const float4* pp = (const float4*)(spA + pair * 512);
            float4 a = pp[lane];
            float4 v1 = pp[lane + 32], v2 = pp[lane + 64], v3 = pp[lane + 96];
            a.x += v1.x + v2.x + v3.x;
            a.y += v1.y + v2.y + v3.y;
            a.z += v1.z + v2.z + v3.z;
            a.w += v1.w + v2.w + v3.w;
            *(float4*)(sp2 + (pair * 32 + lane) * 4) = a;
        }
        __syncthreads();            // sync3: sp2 complete

        // ---- stage2 + online-softmax update (tid<256) ----
        if (tid < 256) {
            int h = tid >> 4;
            int r = (tid >> 2) & 3;
            int q = tid & 3;
            int pair = r * 4 + (h >> 2);
            int j = h & 3;
            const float* pb = sp2 + (pair * 32 + q * 8) * 4 + j;
            float s = ((pb[0] + pb[4]) + (pb[8] + pb[12])) +
                      ((pb[16] + pb[20]) + (pb[24] + pb[28]));
            s += __shfl_xor_sync(0xffffffffu, s, 1);
            s += __shfl_xor_sync(0xffffffffu, s, 2);   // full score(r,h)
            bool act = (fl >> r) & 1;
            float sv = act ? s : -1e30f;
            float m0 = sm_m[h];
            float t = sv;
            t = fmaxf(t, __shfl_xor_sync(0xffffffffu, t, 4));
            t = fmaxf(t, __shfl_xor_sync(0xffffffffu, t, 8));   // max over r
            float nm = fmaxf(t, m0);
            float fac = exp2f((m0 - nm) * L2E);
            float w = act ? exp2f((s - nm) * L2E) : 0.f;
            if (q == 0) sw_[r][h] = w;
            float ws = w;
            ws += __shfl_xor_sync(0xffffffffu, ws, 4);
            ws += __shfl_xor_sync(0xffffffffu, ws, 8);
            if (q == 0 && r == 0) {
                sfac[h] = fac;
                sm_m[h] = nm;
                sm_d[h] = fmaf(fac, sm_d[h], ws);
            }
        }
        __syncthreads();            // sync4: sw_/sfac ready

        // ---- Phase B: rescale + weighted accumulate (rows from REGISTERS) ----
        {
            float4 fv = *(const float4*)&sfac[hg * 4];
            u64 f2[4] = {pack2(fv.x, fv.x), pack2(fv.y, fv.y),
                         pack2(fv.z, fv.z), pack2(fv.w, fv.w)};
#pragma unroll
            for (int j = 0; j < 4; j++)
#pragma unroll
                for (int i = 0; i < 4; i++) ctx[j][i] = fmul2(ctx[j][i], f2[j]);
#pragma unroll
            for (int r = 0; r < RPB; r++) {
                if (!((fl >> r) & 1)) continue;
                float4 wv = *(const float4*)&sw_[r][hg * 4];
                u64 w2[4] = {pack2(wv.x, wv.x), pack2(wv.y, wv.y),
                             pack2(wv.z, wv.z), pack2(wv.w, wv.w)};
#pragma unroll
                for (int j = 0; j < 4; j++) {
                    ctx[j][0] = ffma2(w2[j], xr[r][0], ctx[j][0]);
                    ctx[j][1] = ffma2(w2[j], xr[r][1], ctx[j][1]);
                    ctx[j][2] = ffma2(w2[j], xr[r][2], ctx[j][2]);
                    ctx[j][3] = ffma2(w2[j], xr[r][3], ctx[j][3]);
                }
            }
        }
    }

    // epilogue: unnormalized ctx + per-chunk (m, d)
#pragma unroll
    for (int j = 0; j < 4; j++) {
        float* dst = g_ctxp + (((size_t)chunk * B_ + b) * H_ + hg * 4 + j) * E_;
        float x0, y0, x1, y1;
        unpack2(ctx[j][0], x0, y0);
        unpack2(ctx[j][1], x1, y1);
        *(float4*)(dst + eidx * 4) = make_float4(x0, y0, x1, y1);
        unpack2(ctx[j][2], x0, y0);
        unpack2(ctx[j][3], x1, y1);
        *(float4*)(dst + 512 + eidx * 4) = make_float4(x0, y0, x1, y1);
    }
    if (tid < H_) {
        g_m[(chunk * B_ + b) * H_ + tid] = sm_m[tid];
        g_d[(chunk * B_ + b) * H_ + tid] = sm_d[tid];
    }
}

// ---------------- K4: weighted combine + out = ctx@Wv + bv ----------------
// grid (16 h, 8 bg) block 256
__global__ void k_out(const float* __restrict__ Wv, const float* __restrict__ bv,
                      float* __restrict__ out) {
    int h = blockIdx.x;
    int b0 = blockIdx.y * 4;
    int tid = threadIdx.x;
    int n = tid & 63;
    int qq = tid >> 6;

    __shared__ __align__(16) float sc[4][E_];
    __shared__ float smd[2][4][NC];
    __shared__ float swt[4][NC];

    if (tid < 4 * NC) {
        int bb = tid >> 4, c = tid & 15;
        smd[0][bb][c] = g_m[(c * B_ + b0 + bb) * H_ + h];
        smd[1][bb][c] = g_d[(c * B_ + b0 + bb) * H_ + h];
    }
    __syncthreads();
    if (tid < 4) {
        int bb = tid;
        float M = -1e30f;
#pragma unroll
        for (int c = 0; c < NC; c++) M = fmaxf(M, smd[0][bb][c]);
        float t[NC];
        float Dn = 0.f;
#pragma unroll
        for (int c = 0; c < NC; c++) {
            float e = exp2f((smd[0][bb][c] - M) * L2E);
            t[c] = e;
            Dn += e * smd[1][bb][c];
        }
        float invD = 1.0f / Dn;
#pragma unroll
        for (int c = 0; c < NC; c++) swt[bb][c] = t[c] * invD;
    }
    __syncthreads();

#pragma unroll
    for (int bb = 0; bb < 4; bb++) {
        float4 a = make_float4(0.f, 0.f, 0.f, 0.f);
#pragma unroll
        for (int c = 0; c < NC; c++) {
            float w = swt[bb][c];
            float4 v = ((const float4*)(g_ctxp + (((size_t)c * B_ + b0 + bb) * H_ + h) * E_))[tid];
            a.x = fmaf(w, v.x, a.x);
            a.y = fmaf(w, v.y, a.y);
            a.z = fmaf(w, v.z, a.z);
            a.w = fmaf(w, v.w, a.w);
        }
        ((float4*)sc[bb])[tid] = a;
    }
    __syncthreads();

    int c = h * D_ + n;
    float a0 = 0.f, a1 = 0.f, a2 = 0.f, a3 = 0.f;
#pragma unroll 4
    for (int e = 0; e < 256; e++) {
        float w = Wv[(size_t)(qq * 256 + e) * E_ + c];
        a0 = fmaf(sc[0][qq * 256 + e], w, a0);
        a1 = fmaf(sc[1][qq * 256 + e], w, a1);
        a2 = fmaf(sc[2][qq * 256 + e], w, a2);
        a3 = fmaf(sc[3][qq * 256 + e], w, a3);
    }
    __shared__ float part[4][4][64];
    part[0][qq][n] = a0;
    part[1][qq][n] = a1;
    part[2][qq][n] = a2;
    part[3][qq][n] = a3;
    __syncthreads();
    {
        int bb = tid >> 6, nn = tid & 63;
        float s = (part[bb][0][nn] + part[bb][1][nn]) + (part[bb][2][nn] + part[bb][3][nn]);
        out[(size_t)(b0 + bb) * E_ + h * D_ + nn] = s + bv[h * D_ + nn];
    }
}

// ---------------- launch ----------------
extern "C" void kernel_launch(void* const* d_in, const int* in_sizes, int n_in,
                              void* d_out, int out_size) {
    const float* seq1 = (const float*)d_in[0];
    const float* seq2 = (const float*)d_in[1];
    const int*   mask = (const int*)d_in[2];
    const float* Wq   = (const float*)d_in[3];
    const float* bq   = (const float*)d_in[4];
    const float* Wk   = (const float*)d_in[5];
    // d_in[6] = bk dropped (softmax-invariant uniform shift)
    const float* Wv   = (const float*)d_in[7];
    const float* bv   = (const float*)d_in[8];
    float* out = (float*)d_out;

    const int dynBytes = 65536 + 32768 + 8192;
    cudaFuncSetAttribute(k_fused, cudaFuncAttributeMaxDynamicSharedMemorySize, dynBytes);

    k_qproj<<<dim3(4, 8), 256>>>(seq1, Wq, bq);
    k_qk<<<dim3(H_, 4), 256>>>(Wk);
    k_pad<<<1, 32>>>();
    k_fused<<<dim3(NC, B_), 512, dynBytes>>>(seq2, mask);
    k_out<<<dim3(H_, 8), 256>>>(Wv, bv, out);
}

// round 9
// speedup vs baseline: 1.0847x; 1.0847x over previous
#include <cuda_runtime.h>
#include <cstdint>
#include <cstddef>

#define B_ 32
#define S_ 4096
#define E_ 1024
#define H_ 16
#define HB 8             // heads per block
#define D_ 64
#define NC 16            // chunks over s (256 rows each)
#define RPB 4            // rows per batch
#define NBAT 64          // 256 / RPB
#define L2E 1.4426950408889634f

// ---------------- static scratch ----------------
__device__ float g_q[B_ * E_];
__device__ float g_qk[B_ * H_ * E_];
__device__ float g_ctxp[(size_t)NC * B_ * H_ * E_];   // unnormalized ctx per chunk
__device__ float g_m[NC * B_ * H_];
__device__ float g_d[NC * B_ * H_];

typedef unsigned long long u64;

__device__ __forceinline__ u64 pack2(float x, float y) {
    u64 p;
    asm("mov.b64 %0, {%1, %2};" : "=l"(p) : "f"(x), "f"(y));
    return p;
}
__device__ __forceinline__ void unpack2(u64 p, float& x, float& y) {
    asm("mov.b64 {%0, %1}, %2;" : "=f"(x), "=f"(y) : "l"(p));
}
__device__ __forceinline__ u64 ffma2(u64 a, u64 b, u64 c) {
    u64 d;
    asm("fma.rn.f32x2 %0, %1, %2, %3;" : "=l"(d) : "l"(a), "l"(b), "l"(c));
    return d;
}
__device__ __forceinline__ u64 fmul2(u64 a, u64 b) {
    u64 d;
    asm("mul.rn.f32x2 %0, %1, %2;" : "=l"(d) : "l"(a), "l"(b));
    return d;
}
__device__ __forceinline__ void cp16(uint32_t dst_smem, const void* src) {
    asm volatile("cp.async.cg.shared.global [%0], [%1], 16;" :: "r"(dst_smem), "l"(src));
}
__device__ __forceinline__ void cp_commit() { asm volatile("cp.async.commit_group;"); }
template <int N>
__device__ __forceinline__ void cp_wait() { asm volatile("cp.async.wait_group %0;" :: "n"(N)); }

// ---------------- K1: q = seq1@Wq + bq  (4 b per block) ----------------
__global__ void k_qproj(const float* __restrict__ seq1, const float* __restrict__ Wq,
                        const float* __restrict__ bq) {
    int b0 = blockIdx.y * 4;
    int j = blockIdx.x * 256 + threadIdx.x;
    __shared__ __align__(16) float s1[4][E_];
#pragma unroll
    for (int bb = 0; bb < 4; bb++)
        ((float4*)s1[bb])[threadIdx.x] = ((const float4*)(seq1 + (size_t)(b0 + bb) * E_))[threadIdx.x];
    __syncthreads();
    float acc[4] = {0.f, 0.f, 0.f, 0.f};
#pragma unroll 4
    for (int e = 0; e < E_; e++) {
        float w = Wq[(size_t)e * E_ + j];
#pragma unroll
        for (int bb = 0; bb < 4; bb++) acc[bb] = fmaf(s1[bb][e], w, acc[bb]);
    }
    float bias = bq[j];
#pragma unroll
    for (int bb = 0; bb < 4; bb++) g_q[(b0 + bb) * E_ + j] = acc[bb] + bias;
}

// ---------------- K2: qk[b][h][e] = (Σ_d q[b][h*64+d]·Wk[e][h*64+d]) * 0.125 ----------------
__global__ void k_qk(const float* __restrict__ Wk) {
    int h = blockIdx.x;
    int e = blockIdx.y * 256 + threadIdx.x;
    __shared__ __align__(16) float2 sq[B_][D_ / 2];
    for (int i = threadIdx.x; i < B_ * (D_ / 2); i += 256) {
        int b = i >> 5, dp = i & 31;
        sq[b][dp] = ((const float2*)(g_q + b * E_ + h * D_))[dp];
    }
    __syncthreads();
    float2 wk[D_ / 2];
    const float2* wrow = (const float2*)(Wk + (size_t)e * E_ + h * D_);
#pragma unroll
    for (int i = 0; i < D_ / 2; i++) wk[i] = wrow[i];
#pragma unroll 4
    for (int b = 0; b < B_; b++) {
        float ax = 0.f, ay = 0.f;
#pragma unroll
        for (int i = 0; i < D_ / 2; i++) {
            float2 qv = sq[b][i];
            ax = fmaf(wk[i].x, qv.x, ax);
            ay = fmaf(wk[i].y, qv.y, ay);
        }
        g_qk[(b * H_ + h) * E_ + e] = (ax + ay) * 0.125f;
    }
}

// ---------------- pad kernel (keeps ncu sample index on k_fused) ----------------
__global__ void k_pad() {}

// ---------------- K3: fused scores + online softmax + ctx (8 heads/block) ----------------
// grid (2 hb, NC, B_) block 512, 2 blocks/SM
// thread: hg = tid>>8 (0..1) -> 4 heads hb*8+hg*4+j ; eidx = tid&255 -> float4 at eidx*4
// dyn smem: sx[3][RPB][1024] 48KB + spA[8][256]f4 32KB + sp2[8][65]f4 8.32KB
#define SP2S 65
__global__ void __launch_bounds__(512, 2) k_fused(const float* __restrict__ seq2,
                                                  const int* __restrict__ mask) {
    extern __shared__ __align__(16) char dyn[];
    float* sx  = (float*)dyn;                        // [3][RPB][1024]
    float* spA = (float*)(dyn + 49152);              // [(r*2+hg)][eidx] float4
    float* sp2 = (float*)(dyn + 49152 + 32768);      // [p][SP2S] float4
    __shared__ float sw_[RPB][HB];
    __shared__ float sfac[HB];
    __shared__ float sm_m[HB], sm_d[HB];
    __shared__ uint32_t sball[8];

    int hb = blockIdx.x;
    int chunk = blockIdx.y;
    int b = blockIdx.z;
    int s0 = chunk * 256;
    int tid = threadIdx.x;
    int hg = tid >> 8;              // 0..1
    int eidx = tid & 255;           // 0..255

    if (tid < 256) {
        int mm = mask[b * S_ + s0 + tid];
        uint32_t bal = __ballot_sync(0xffffffffu, mm != 0);
        if ((tid & 31) == 0) sball[tid >> 5] = bal;
    }
    if (tid < HB) { sm_m[tid] = -1e30f; sm_d[tid] = 0.f; }

    // qk regs: 4 heads x 4 floats
    u64 qk2[4][2];
#pragma unroll
    for (int j = 0; j < 4; j++) {
        const float* qb = g_qk + ((size_t)b * H_ + hb * HB + hg * 4 + j) * E_;
        float4 v = *(const float4*)(qb + eidx * 4);
        qk2[j][0] = pack2(v.x, v.y);
        qk2[j][1] = pack2(v.z, v.w);
    }

    u64 ctx[4][2];
#pragma unroll
    for (int j = 0; j < 4; j++) {
        ctx[j][0] = pack2(0.f, 0.f);
        ctx[j][1] = pack2(0.f, 0.f);
    }

    uint32_t sx_addr = (uint32_t)__cvta_generic_to_shared(sx);
    const float* base = seq2 + ((size_t)b * S_ + s0) * E_;
    int srow = tid >> 7;            // 0..3 staging row
    int scol = tid & 127;           // 8 floats per thread per row

    __syncthreads();                // sball / sm_* visible

    // prologue: prefetch batches 0,1
#pragma unroll
    for (int nb = 0; nb < 2; nb++) {
        uint32_t flN = (sball[0] >> (nb * 4)) & 0xF;
        if ((flN >> srow) & 1) {
            const float* src = base + ((size_t)nb * RPB + srow) * E_ + scol * 8;
            uint32_t dst = sx_addr + (uint32_t)(nb * RPB + srow) * 4096 + scol * 32;
            cp16(dst, src);
            cp16(dst + 16, src + 4);
        }
        cp_commit();
    }

    for (int bat = 0; bat < NBAT; bat++) {
        int stage = bat % 3;
        {   // prefetch bat+2 (one commit per iter keeps accounting uniform)
            int nb = bat + 2;
            if (nb < NBAT) {
                uint32_t flN = (sball[nb >> 3] >> ((nb & 7) * 4)) & 0xF;
                if ((flN >> srow) & 1) {
                    const float* src = base + ((size_t)nb * RPB + srow) * E_ + scol * 8;
                    uint32_t dst = sx_addr + (uint32_t)((nb % 3) * RPB + srow) * 4096 + scol * 32;
                    cp16(dst, src);
                    cp16(dst + 16, src + 4);
                }
            }
            cp_commit();
        }
        cp_wait<2>();
        __syncthreads();            // sync1: batch data ready

        uint32_t fl = (sball[bat >> 3] >> ((bat & 7) * 4)) & 0xF;
        if (fl == 0) continue;      // block-uniform skip

        const float* xs = sx + stage * (RPB * 1024);

        // ---- Phase A: row dot partials, float4 STS ----
#pragma unroll
        for (int r = 0; r < RPB; r++) {
            if ((fl >> r) & 1) {
                float4 xv = *(const float4*)(xs + r * 1024 + eidx * 4);
                u64 x0 = pack2(xv.x, xv.y), x1 = pack2(xv.z, xv.w);
                float pj[4];
#pragma unroll
                for (int j = 0; j < 4; j++) {
                    u64 a = fmul2(qk2[j][0], x0);
                    a = ffma2(qk2[j][1], x1, a);
                    float ax, ay;
                    unpack2(a, ax, ay);
                    pj[j] = ax + ay;
                }
                *(float4*)(spA + ((r * 2 + hg) * 256 + eidx) * 4) =
                    make_float4(pj[0], pj[1], pj[2], pj[3]);
            }
        }
        __syncthreads();            // sync2: spA done

        // ---- stage1: 256 -> 64 per (r,hg), float4-wide ----
        {
            int p = tid >> 6, i = tid & 63;
            const float4* pp = (const float4*)(spA + p * 1024);
            float4 a = pp[i];
            float4 v1 = pp[i + 64], v2 = pp[i + 128], v3 = pp[i + 192];
            a.x += v1.x + v2.x + v3.x;
            a.y += v1.y + v2.y + v3.y;
            a.z += v1.z + v2.z + v3.z;
            a.w += v1.w + v2.w + v3.w;
            *(float4*)(sp2 + (p * SP2S + i) * 4) = a;
        }
        __syncthreads();            // sync3: sp2 done

        // ---- stage2 + online softmax: one warp per head ----
        if (tid < 256) {
            int h = tid >> 5;                 // 0..7 (warp per head)
            int r = (tid >> 3) & 3;
            int q = tid & 7;
            int p = r * 2 + (h >> 2);
            int j = h & 3;
            const float* pb = sp2 + (p * SP2S + q) * 4 + j;
            float s = 0.f;
#pragma unroll
            for (int k = 0; k < 8; k++) s += pb[k * 32];   // idx = q + 8k
            s += __shfl_xor_sync(0xffffffffu, s, 1);
            s += __shfl_xor_sync(0xffffffffu, s, 2);
            s += __shfl_xor_sync(0xffffffffu, s, 4);       // full score(r,h)
            bool act = (fl >> r) & 1;
            float sv = act ? s : -1e30f;
            float m0 = sm_m[h];
            float t = sv;
            t = fmaxf(t, __shfl_xor_sync(0xffffffffu, t, 8));
            t = fmaxf(t, __shfl_xor_sync(0xffffffffu, t, 16));   // max over r
            float nm = fmaxf(t, m0);
            float fac = exp2f((m0 - nm) * L2E);
            float w = act ? exp2f((s - nm) * L2E) : 0.f;
            if (q == 0) sw_[r][h] = w;
            float ws = w;
            ws += __shfl_xor_sync(0xffffffffu, ws, 8);
            ws += __shfl_xor_sync(0xffffffffu, ws, 16);
            if (q == 0 && r == 0) {
                sfac[h] = fac;
                sm_m[h] = nm;
                sm_d[h] = fmaf(fac, sm_d[h], ws);
            }
        }
        __syncthreads();            // sync4: sw_/sfac ready

        // ---- Phase B: rescale + weighted accumulate ----
        {
            float4 fv = *(const float4*)&sfac[hg * 4];
            u64 f2[4] = {pack2(fv.x, fv.x), pack2(fv.y, fv.y),
                         pack2(fv.z, fv.z), pack2(fv.w, fv.w)};
#pragma unroll
            for (int j = 0; j < 4; j++) {
                ctx[j][0] = fmul2(ctx[j][0], f2[j]);
                ctx[j][1] = fmul2(ctx[j][1], f2[j]);
            }
#pragma unroll
            for (int r = 0; r < RPB; r++) {
                if (!((fl >> r) & 1)) continue;
                float4 wv = *(const float4*)&sw_[r][hg * 4];
                u64 w2[4] = {pack2(wv.x, wv.x), pack2(wv.y, wv.y),
                             pack2(wv.z, wv.z), pack2(wv.w, wv.w)};
                float4 xv = *(const float4*)(xs + r * 1024 + eidx * 4);
                u64 x0 = pack2(xv.x, xv.y), x1 = pack2(xv.z, xv.w);
#pragma unroll
                for (int j = 0; j < 4; j++) {
                    ctx[j][0] = ffma2(w2[j], x0, ctx[j][0]);
                    ctx[j][1] = ffma2(w2[j], x1, ctx[j][1]);
                }
            }
        }
    }

    // epilogue: unnormalized ctx + per-chunk (m, d)
#pragma unroll
    for (int j = 0; j < 4; j++) {
        float* dst = g_ctxp +
            (((size_t)chunk * B_ + b) * H_ + hb * HB + hg * 4 + j) * E_ + eidx * 4;
        float x0, y0, x1, y1;
        unpack2(ctx[j][0], x0, y0);
        unpack2(ctx[j][1], x1, y1);
        *(float4*)dst = make_float4(x0, y0, x1, y1);
    }
    if (tid < HB) {
        g_m[(chunk * B_ + b) * H_ + hb * HB + tid] = sm_m[tid];
        g_d[(chunk * B_ + b) * H_ + tid + hb * HB] = sm_d[tid];
    }
}

// ---------------- K4: weighted combine + out = ctx@Wv + bv ----------------
// grid (16 h, 8 bg) block 256
__global__ void k_out(const float* __restrict__ Wv, const float* __restrict__ bv,
                      float* __restrict__ out) {
    int h = blockIdx.x;
    int b0 = blockIdx.y * 4;
    int tid = threadIdx.x;
    int n = tid & 63;
    int qq = tid >> 6;

    __shared__ __align__(16) float sc[4][E_];
    __shared__ float smd[2][4][NC];
    __shared__ float swt[4][NC];

    if (tid < 4 * NC) {
        int bb = tid >> 4, c = tid & 15;
        smd[0][bb][c] = g_m[(c * B_ + b0 + bb) * H_ + h];
        smd[1][bb][c] = g_d[(c * B_ + b0 + bb) * H_ + h];
    }
    __syncthreads();
    if (tid < 4) {
        int bb = tid;
        float M = -1e30f;
#pragma unroll
        for (int c = 0; c < NC; c++) M = fmaxf(M, smd[0][bb][c]);
        float t[NC];
        float Dn = 0.f;
#pragma unroll
        for (int c = 0; c < NC; c++) {
            float e = exp2f((smd[0][bb][c] - M) * L2E);
            t[c] = e;
            Dn += e * smd[1][bb][c];
        }
        float invD = 1.0f / Dn;
#pragma unroll
        for (int c = 0; c < NC; c++) swt[bb][c] = t[c] * invD;
    }
    __syncthreads();

#pragma unroll
    for (int bb = 0; bb < 4; bb++) {
        float4 a = make_float4(0.f, 0.f, 0.f, 0.f);
#pragma unroll
        for (int c = 0; c < NC; c++) {
            float w = swt[bb][c];
            float4 v = ((const float4*)(g_ctxp + (((size_t)c * B_ + b0 + bb) * H_ + h) * E_))[tid];
            a.x = fmaf(w, v.x, a.x);
            a.y = fmaf(w, v.y, a.y);
            a.z = fmaf(w, v.z, a.z);
            a.w = fmaf(w, v.w, a.w);
        }
        ((float4*)sc[bb])[tid] = a;
    }
    __syncthreads();

    int c = h * D_ + n;
    float a0 = 0.f, a1 = 0.f, a2 = 0.f, a3 = 0.f;
#pragma unroll 4
    for (int e = 0; e < 256; e++) {
        float w = Wv[(size_t)(qq * 256 + e) * E_ + c];
        a0 = fmaf(sc[0][qq * 256 + e], w, a0);
        a1 = fmaf(sc[1][qq * 256 + e], w, a1);
        a2 = fmaf(sc[2][qq * 256 + e], w, a2);
        a3 = fmaf(sc[3][qq * 256 + e], w, a3);
    }
    __shared__ float part[4][4][64];
    part[0][qq][n] = a0;
    part[1][qq][n] = a1;
    part[2][qq][n] = a2;
    part[3][qq][n] = a3;
    __syncthreads();
    {
        int bb = tid >> 6, nn = tid & 63;
        float s = (part[bb][0][nn] + part[bb][1][nn]) + (part[bb][2][nn] + part[bb][3][nn]);
        out[(size_t)(b0 + bb) * E_ + h * D_ + nn] = s + bv[h * D_ + nn];
    }
}

// ---------------- launch ----------------
extern "C" void kernel_launch(void* const* d_in, const int* in_sizes, int n_in,
                              void* d_out, int out_size) {
    const float* seq1 = (const float*)d_in[0];
    const float* seq2 = (const float*)d_in[1];
    const int*   mask = (const int*)d_in[2];
    const float* Wq   = (const float*)d_in[3];
    const float* bq   = (const float*)d_in[4];
    const float* Wk   = (const float*)d_in[5];
    // d_in[6] = bk dropped (softmax-invariant uniform shift)
    const float* Wv   = (const float*)d_in[7];
    const float* bv   = (const float*)d_in[8];
    float* out = (float*)d_out;

    const int dynBytes = 49152 + 32768 + 8 * SP2S * 16;   // 48K + 32K + 8.32K
    cudaFuncSetAttribute(k_fused, cudaFuncAttributeMaxDynamicSharedMemorySize, dynBytes);

    k_qproj<<<dim3(4, 8), 256>>>(seq1, Wq, bq);
    k_qk<<<dim3(H_, 4), 256>>>(Wk);
    k_pad<<<1, 32>>>();
    k_fused<<<dim3(2, NC, B_), 512, dynBytes>>>(seq2, mask);
    k_out<<<dim3(H_, 8), 256>>>(Wv, bv, out);
}